// round 9
// baseline (speedup 1.0000x reference)
#include <cuda_runtime.h>
#include <math.h>
#include <stdint.h>

// ---------------- problem constants ----------------
#define BB      64
#define NP      377
#define NROWS   (BB * NP)        // 24128 = 377 * 64
#define CIN     384
#define HID     128
#define H2X     256
#define SD      16
#define KNEI    6
#define PIN_DIM (SD * (KNEI + 1)) // 112
#define NSTEPS  16
#define FH      37
#define DHH     518

// pair-interleaved layouts:
// A: addr = blk*A_BO + p*A_S + m*2 + idx   (blk=k>>3, p=k&3, idx=(k>>2)&1)
// W: addr = blk*W_BO + p*W_S + n*2 + idx
#define A_S   136     // mod 32 == 8  -> frag loads conflict-free
#define A_BO  560     // mod 32 == 16 -> staging stores conflict-free
#define ABUF  1120    // 2 blks
#define W_S   264     // mod 32 == 8
#define W_BO  1058    // mod 32 == 2
#define WBUF  2116

// gemm smem (floats)
#define GAH 0
#define GAL 2240
#define GWH 4480
#define GWL 8712
#define G2_TOTAL_F 12944
#define G2_TOTAL_B (G2_TOTAL_F * 4)    // 51776

// fused smem (floats)
#define FAH 0
#define FAL 2240
#define FWH 4480
#define FWL 8712
#define FHH 12944                      // Hs pair layout: 16 blks * 560 = 8960
#define FHL 21904
#define FB1 30864
#define FB2 30992
#define FB3 31120
#define F2_TOTAL_F 31136
#define F2_TOTAL_B (F2_TOTAL_F * 4)    // 124544

// ---------------- tf32 helpers ----------------------------------------------
__device__ __forceinline__ float tf32_rnd(float x) {
    uint32_t r;
    asm("cvt.rna.tf32.f32 %0, %1;" : "=r"(r) : "f"(x));
    return __uint_as_float(r);
}
__device__ __forceinline__ void split_tf32(float x, float& hi, float& lo) {
    hi = tf32_rnd(x);
    lo = tf32_rnd(x - hi);
}
__device__ __forceinline__ void mma8(float* d, const uint32_t* a, const uint32_t* b) {
    asm volatile(
        "mma.sync.aligned.m16n8k8.row.col.f32.tf32.tf32.f32 "
        "{%0,%1,%2,%3}, {%4,%5,%6,%7}, {%8,%9}, {%0,%1,%2,%3};"
        : "+f"(d[0]), "+f"(d[1]), "+f"(d[2]), "+f"(d[3])
        : "r"(a[0]), "r"(a[1]), "r"(a[2]), "r"(a[3]), "r"(b[0]), "r"(b[1]));
}

// fragment loaders from pair layout (float2 = both k-values)
__device__ __forceinline__ void frag_a(uint32_t a[4], const float* base, int cc, int m) {
    float2 v0 = *reinterpret_cast<const float2*>(base + cc * A_S + m * 2);
    float2 v1 = *reinterpret_cast<const float2*>(base + cc * A_S + (m + 8) * 2);
    a[0] = __float_as_uint(v0.x);
    a[1] = __float_as_uint(v1.x);
    a[2] = __float_as_uint(v0.y);
    a[3] = __float_as_uint(v1.y);
}
__device__ __forceinline__ void frag_b(uint32_t b[2], const float* base, int cc, int n) {
    float2 v = *reinterpret_cast<const float2*>(base + cc * W_S + n * 2);
    b[0] = __float_as_uint(v.x);
    b[1] = __float_as_uint(v.y);
}

// one k8 block: 32x32 warp tile (2 m-subtiles x 4 n-subtiles), 3xTF32
__device__ __forceinline__ void tc_k8(float d[2][4][4],
                                      const float* aH, const float* aL,
                                      const float* wH, const float* wL,
                                      int cc, int r, int mbase, int nbase) {
    uint32_t ahi[2][4], alo[2][4];
    frag_a(ahi[0], aH, cc, mbase + r);
    frag_a(alo[0], aL, cc, mbase + r);
    frag_a(ahi[1], aH, cc, mbase + 16 + r);
    frag_a(alo[1], aL, cc, mbase + 16 + r);
#pragma unroll
    for (int nt = 0; nt < 4; nt++) {
        uint32_t bh[2], bl[2];
        frag_b(bh, wH, cc, nbase + 8 * nt + r);
        frag_b(bl, wL, cc, nbase + 8 * nt + r);
#pragma unroll
        for (int mt = 0; mt < 2; mt++) {
            mma8(d[mt][nt], alo[mt], bh);
            mma8(d[mt][nt], ahi[mt], bl);
            mma8(d[mt][nt], ahi[mt], bh);
        }
    }
}

// staging: A (64x16 tile), thread holds float4 of 4 consecutive k at one m
__device__ __forceinline__ void stage_a(float* AH, float* AL, float4 v, int am, int aq) {
    int blk = aq >> 3, idx = (aq >> 2) & 1;
    float* ph = AH + blk * A_BO + am * 2 + idx;
    float* pl = AL + blk * A_BO + am * 2 + idx;
    float h, l;
    split_tf32(v.x, h, l); ph[0 * A_S] = h; pl[0 * A_S] = l;
    split_tf32(v.y, h, l); ph[1 * A_S] = h; pl[1 * A_S] = l;
    split_tf32(v.z, h, l); ph[2 * A_S] = h; pl[2 * A_S] = l;
    split_tf32(v.w, h, l); ph[3 * A_S] = h; pl[3 * A_S] = l;
}
// staging: W (16x128 tile), thread holds 8 consecutive n at one k row
__device__ __forceinline__ void stage_w(float* WH, float* WL, float4 w0, float4 w1,
                                        int wk, int wn8) {
    int blk = wk >> 3, p = wk & 3, idx = (wk >> 2) & 1;
    float* ph = WH + blk * W_BO + p * W_S + wn8 * 2 + idx;
    float* pl = WL + blk * W_BO + p * W_S + wn8 * 2 + idx;
    float h, l;
    split_tf32(w0.x, h, l); ph[0] = h;  pl[0] = l;
    split_tf32(w0.y, h, l); ph[2] = h;  pl[2] = l;
    split_tf32(w0.z, h, l); ph[4] = h;  pl[4] = l;
    split_tf32(w0.w, h, l); ph[6] = h;  pl[6] = l;
    split_tf32(w1.x, h, l); ph[8] = h;  pl[8] = l;
    split_tf32(w1.y, h, l); ph[10] = h; pl[10] = l;
    split_tf32(w1.z, h, l); ph[12] = h; pl[12] = l;
    split_tf32(w1.w, h, l); ph[14] = h; pl[14] = l;
}

// ---------------- scratch ----------------------------------------------------
__device__ float g_Fs[(size_t)NROWS * CIN];
__device__ float g_dep[NROWS];
__device__ float g_bufA[(size_t)NROWS * H2X];
__device__ float g_bufB[(size_t)NROWS * HID];
__device__ float g_init[(size_t)NROWS * SD];
__device__ float g_state[(size_t)NROWS * SD];
__device__ float g_pin[(size_t)NROWS * PIN_DIM];

// ---------------- feature bilinear sampling ----------------------------------
__global__ void sample_feat_kernel(const float* __restrict__ feat,
                                   const float* __restrict__ sx,
                                   const float* __restrict__ sy) {
    int row = blockIdx.x;
    int b = row / NP, n = row % NP;
    float gx = sx[n], gy = sy[n];

    float ix = fminf(fmaxf((gx + 1.0f) * 0.5f * (float)(FH - 1), 0.0f), (float)(FH - 1));
    float iy = fminf(fmaxf((gy + 1.0f) * 0.5f * (float)(FH - 1), 0.0f), (float)(FH - 1));
    int x0 = (int)floorf(ix), y0 = (int)floorf(iy);
    int x1 = min(x0 + 1, FH - 1), y1 = min(y0 + 1, FH - 1);
    float wx = ix - (float)x0, wy = iy - (float)y0;
    float w00 = (1.0f - wx) * (1.0f - wy);
    float w01 = wx * (1.0f - wy);
    float w10 = (1.0f - wx) * wy;
    float w11 = wx * wy;

    const float* fb = feat + (size_t)b * CIN * FH * FH;
    for (int c = threadIdx.x; c < CIN; c += blockDim.x) {
        const float* p = fb + (size_t)c * FH * FH;
        float v = p[y0 * FH + x0] * w00 + p[y0 * FH + x1] * w01 +
                  p[y1 * FH + x0] * w10 + p[y1 * FH + x1] * w11;
        g_Fs[(size_t)row * CIN + c] = v;
    }
}

// ---------------- depth bilinear sampling ------------------------------------
__global__ void sample_depth_kernel(const float* __restrict__ depth,
                                    const float* __restrict__ sx,
                                    const float* __restrict__ sy) {
    int row = blockIdx.x * blockDim.x + threadIdx.x;
    if (row >= NROWS) return;
    int b = row / NP, n = row % NP;
    float gx = sx[n], gy = sy[n];
    float jx = fminf(fmaxf((gx + 1.0f) * 0.5f * (float)(DHH - 1), 0.0f), (float)(DHH - 1));
    float jy = fminf(fmaxf((gy + 1.0f) * 0.5f * (float)(DHH - 1), 0.0f), (float)(DHH - 1));
    int a0 = (int)floorf(jx), c0 = (int)floorf(jy);
    int a1 = min(a0 + 1, DHH - 1), c1 = min(c0 + 1, DHH - 1);
    float ux = jx - (float)a0, uy = jy - (float)c0;
    const float* dp = depth + (size_t)b * DHH * DHH;
    float v = dp[c0 * DHH + a0] * (1.0f - ux) * (1.0f - uy) +
              dp[c0 * DHH + a1] * ux * (1.0f - uy) +
              dp[c1 * DHH + a0] * (1.0f - ux) * uy +
              dp[c1 * DHH + a1] * ux * uy;
    g_dep[row] = v;
}

// ---------------- tensor-core 64x128 GEMM (relu epilogue) --------------------
// 256 threads, 8 warps, 32x32 warp tiles, pair-interleaved smem, double-buffered.
__global__ void __launch_bounds__(256, 2)
gemm_tc(const float* __restrict__ A, const float* __restrict__ W,
        const float* __restrict__ bias, float* __restrict__ C,
        int K, int N) {
    extern __shared__ float dyn[];
    float* AH = dyn + GAH;
    float* AL = dyn + GAL;
    float* WH = dyn + GWH;
    float* WL = dyn + GWL;

    int m0 = blockIdx.x * 64;
    int n0 = blockIdx.y * 128;
    int tid = threadIdx.x;
    int warp = tid >> 5, lane = tid & 31;
    int wm = warp >> 2, wnq = warp & 3;
    int mbase = 32 * wm, nbase = 32 * wnq;
    int r = lane >> 2, cc = lane & 3;

    int am = tid >> 2, aq = (tid & 3) * 4;
    int wk = tid >> 4, wn8 = (tid & 15) * 8;

    float d[2][4][4];
#pragma unroll
    for (int i = 0; i < 2; i++)
#pragma unroll
        for (int j = 0; j < 4; j++)
#pragma unroll
            for (int k = 0; k < 4; k++) d[i][j][k] = 0.0f;

    // preload tile 0
    {
        float4 va = *reinterpret_cast<const float4*>(&A[(size_t)(m0 + am) * K + aq]);
        float4 w0 = *reinterpret_cast<const float4*>(&W[(size_t)wk * N + n0 + wn8]);
        float4 w1 = *reinterpret_cast<const float4*>(&W[(size_t)wk * N + n0 + wn8 + 4]);
        stage_a(AH, AL, va, am, aq);
        stage_w(WH, WL, w0, w1, wk, wn8);
    }
    __syncthreads();

    int KT = K >> 4;
    int p = 0;
    for (int t = 0; t < KT; t++) {
        float4 pa, pw0, pw1;
        bool has = (t + 1 < KT);
        if (has) {
            int k0 = (t + 1) << 4;
            pa  = *reinterpret_cast<const float4*>(&A[(size_t)(m0 + am) * K + k0 + aq]);
            pw0 = *reinterpret_cast<const float4*>(&W[(size_t)(k0 + wk) * N + n0 + wn8]);
            pw1 = *reinterpret_cast<const float4*>(&W[(size_t)(k0 + wk) * N + n0 + wn8 + 4]);
        }

#pragma unroll
        for (int blk = 0; blk < 2; blk++)
            tc_k8(d, AH + p * ABUF + blk * A_BO, AL + p * ABUF + blk * A_BO,
                     WH + p * WBUF + blk * W_BO, WL + p * WBUF + blk * W_BO,
                     cc, r, mbase, nbase);

        if (has) {
            int q = p ^ 1;
            stage_a(AH + q * ABUF, AL + q * ABUF, pa, am, aq);
            stage_w(WH + q * WBUF, WL + q * WBUF, pw0, pw1, wk, wn8);
        }
        __syncthreads();
        p ^= 1;
    }

    // epilogue
#pragma unroll
    for (int mt = 0; mt < 2; mt++) {
        int row0 = m0 + mbase + 16 * mt + r;
#pragma unroll
        for (int nt = 0; nt < 4; nt++) {
            int col = n0 + nbase + 8 * nt + 2 * cc;
            float b0 = bias[col], b1 = bias[col + 1];
            float v0 = fmaxf(d[mt][nt][0] + b0, 0.0f);
            float v1 = fmaxf(d[mt][nt][1] + b1, 0.0f);
            float v2 = fmaxf(d[mt][nt][2] + b0, 0.0f);
            float v3 = fmaxf(d[mt][nt][3] + b1, 0.0f);
            *reinterpret_cast<float2*>(&C[(size_t)row0 * N + col]) = make_float2(v0, v1);
            *reinterpret_cast<float2*>(&C[(size_t)(row0 + 8) * N + col]) = make_float2(v2, v3);
        }
    }
}

// ---------------- small GEMM (N=16), used once for wi3 -----------------------
template <int BM, int BN, int BK, int TM, int TN, int EPI>
__global__ void gemm_kernel(const float* __restrict__ A,
                            const float* __restrict__ W,
                            const float* __restrict__ bias,
                            float* __restrict__ C,
                            int K, int N) {
    constexpr int TX = BN / TN;
    constexpr int TY = BM / TM;
    static_assert(TX * TY == 256, "256 threads");
    constexpr int AS = BM + 4;
    __shared__ float As[BK][AS];
    __shared__ float Ws[BK][BN];

    int m0 = blockIdx.x * BM;
    int n0 = blockIdx.y * BN;
    int tid = threadIdx.x;
    int tx = tid % TX, ty = tid / TX;

    float acc[TM][TN];
#pragma unroll
    for (int i = 0; i < TM; i++)
#pragma unroll
        for (int j = 0; j < TN; j++) acc[i][j] = 0.0f;

    int am = tid >> 2;
    int aq = (tid & 3) * 4;

    for (int k0 = 0; k0 < K; k0 += BK) {
        {
            const float4 v = *reinterpret_cast<const float4*>(
                &A[(size_t)(m0 + am) * K + k0 + aq]);
            As[aq + 0][am] = v.x;
            As[aq + 1][am] = v.y;
            As[aq + 2][am] = v.z;
            As[aq + 3][am] = v.w;
        }
        for (int i = tid; i < BK * BN; i += 256) {
            int k = i / BN, n = i % BN;
            Ws[k][n] = W[(size_t)(k0 + k) * N + n0 + n];
        }
        __syncthreads();
#pragma unroll
        for (int kk = 0; kk < BK; kk++) {
            float a[TM], w[TN];
#pragma unroll
            for (int i = 0; i < TM; i++) a[i] = As[kk][ty * TM + i];
#pragma unroll
            for (int j = 0; j < TN; j++) w[j] = Ws[kk][tx * TN + j];
#pragma unroll
            for (int i = 0; i < TM; i++)
#pragma unroll
                for (int j = 0; j < TN; j++) acc[i][j] += a[i] * w[j];
        }
        __syncthreads();
    }
#pragma unroll
    for (int i = 0; i < TM; i++) {
        int m = m0 + ty * TM + i;
#pragma unroll
        for (int j = 0; j < TN; j++) {
            int n = n0 + tx * TN + j;
            float v = acc[i][j] + bias[n];
            if (EPI == 0) v = fmaxf(v, 0.0f);
            C[(size_t)m * N + n] = v;
        }
    }
}

// store h2 value into Hs pair layout (k = phase-2 k index, m = row)
__device__ __forceinline__ void hstore(float* HH, float* HL, int k, int m, float v) {
    int blk = k >> 3, pp = k & 3, idx = (k >> 2) & 1;
    int off = blk * A_BO + pp * A_S + m * 2 + idx;
    float h, l;
    split_tf32(v, h, l);
    HH[off] = h;
    HL[off] = l;
}

// ---------------- fused wp2 -> wu1 -> wu2 -> state update (tensor core) ------
__global__ void __launch_bounds__(256, 1)
fused_step(const float* __restrict__ A,           // g_bufA (h1), row len 256
           const float* __restrict__ wp2, const float* __restrict__ bp2,
           const float* __restrict__ wu1, const float* __restrict__ bu1,
           const float* __restrict__ wu2, const float* __restrict__ bu2,
           const float* __restrict__ sstep,
           float* __restrict__ state) {
    extern __shared__ float dyn[];
    float* AH = dyn + FAH;
    float* AL = dyn + FAL;
    float* WH = dyn + FWH;
    float* WL = dyn + FWL;
    float* HsH = dyn + FHH;
    float* HsL = dyn + FHL;
    float* bp2s = dyn + FB1;
    float* bu1s = dyn + FB2;
    float* bu2s = dyn + FB3;
    float* Hc = dyn;                 // dh compact [128][68], aliases A/W staging
    float* wu2s = dyn + FWL;         // wu2 staging, aliases WL (post-phase-2)

    int m0 = blockIdx.x * 64;
    int tid = threadIdx.x;
    int warp = tid >> 5, lane = tid & 31;
    int wm = warp >> 2, wnq = warp & 3;
    int mbase = 32 * wm, nbase = 32 * wnq;
    int r = lane >> 2, cc = lane & 3;

    int am = tid >> 2, aq = (tid & 3) * 4;
    int wk = tid >> 4, wn8 = (tid & 15) * 8;

    if (tid < 128) { bp2s[tid] = bp2[tid]; bu1s[tid] = bu1[tid]; }
    if (tid < 16)  { bu2s[tid] = bu2[tid]; }

    float d[2][4][4];
#pragma unroll
    for (int i = 0; i < 2; i++)
#pragma unroll
        for (int j = 0; j < 4; j++)
#pragma unroll
            for (int k = 0; k < 4; k++) d[i][j][k] = 0.0f;

    // ---- phase 1: h2 = relu(h1 @ wp2 + bp2), K=256 ----
    {
        float4 va = *reinterpret_cast<const float4*>(&A[(size_t)(m0 + am) * 256 + aq]);
        float4 w0 = *reinterpret_cast<const float4*>(&wp2[(size_t)wk * 128 + wn8]);
        float4 w1 = *reinterpret_cast<const float4*>(&wp2[(size_t)wk * 128 + wn8 + 4]);
        stage_a(AH, AL, va, am, aq);
        stage_w(WH, WL, w0, w1, wk, wn8);
    }
    __syncthreads();

    int p = 0;
    for (int t = 0; t < 16; t++) {
        float4 pa, pw0, pw1;
        bool has = (t + 1 < 16);
        if (has) {
            int k0 = (t + 1) << 4;
            pa  = *reinterpret_cast<const float4*>(&A[(size_t)(m0 + am) * 256 + k0 + aq]);
            pw0 = *reinterpret_cast<const float4*>(&wp2[(size_t)(k0 + wk) * 128 + wn8]);
            pw1 = *reinterpret_cast<const float4*>(&wp2[(size_t)(k0 + wk) * 128 + wn8 + 4]);
        }
#pragma unroll
        for (int blk = 0; blk < 2; blk++)
            tc_k8(d, AH + p * ABUF + blk * A_BO, AL + p * ABUF + blk * A_BO,
                     WH + p * WBUF + blk * W_BO, WL + p * WBUF + blk * W_BO,
                     cc, r, mbase, nbase);
        if (has) {
            int q = p ^ 1;
            stage_a(AH + q * ABUF, AL + q * ABUF, pa, am, aq);
            stage_w(WH + q * WBUF, WL + q * WBUF, pw0, pw1, wk, wn8);
        }
        __syncthreads();
        p ^= 1;
    }

    // epilogue 1: h2 -> Hs pair layout; stage wu1 tile 0
#pragma unroll
    for (int mt = 0; mt < 2; mt++) {
        int row = mbase + 16 * mt + r;
#pragma unroll
        for (int nt = 0; nt < 4; nt++) {
            int col = nbase + 8 * nt + 2 * cc;
            float b0 = bp2s[col], b1 = bp2s[col + 1];
            hstore(HsH, HsL, col,     row,     fmaxf(d[mt][nt][0] + b0, 0.0f));
            hstore(HsH, HsL, col + 1, row,     fmaxf(d[mt][nt][1] + b1, 0.0f));
            hstore(HsH, HsL, col,     row + 8, fmaxf(d[mt][nt][2] + b0, 0.0f));
            hstore(HsH, HsL, col + 1, row + 8, fmaxf(d[mt][nt][3] + b1, 0.0f));
        }
    }
    {
        float4 w0 = *reinterpret_cast<const float4*>(&wu1[(size_t)wk * 128 + wn8]);
        float4 w1 = *reinterpret_cast<const float4*>(&wu1[(size_t)wk * 128 + wn8 + 4]);
        stage_w(WH, WL, w0, w1, wk, wn8);
    }
    __syncthreads();

    // ---- phase 2: dh = relu(h2 @ wu1 + bu1), K=128, A resident in Hs ----
#pragma unroll
    for (int i = 0; i < 2; i++)
#pragma unroll
        for (int j = 0; j < 4; j++)
#pragma unroll
            for (int k = 0; k < 4; k++) d[i][j][k] = 0.0f;

    p = 0;
    for (int c = 0; c < 8; c++) {
        float4 pw0, pw1;
        bool has = (c + 1 < 8);
        if (has) {
            int k0 = (c + 1) << 4;
            pw0 = *reinterpret_cast<const float4*>(&wu1[(size_t)(k0 + wk) * 128 + wn8]);
            pw1 = *reinterpret_cast<const float4*>(&wu1[(size_t)(k0 + wk) * 128 + wn8 + 4]);
        }
#pragma unroll
        for (int blk = 0; blk < 2; blk++)
            tc_k8(d, HsH + (2 * c + blk) * A_BO, HsL + (2 * c + blk) * A_BO,
                     WH + p * WBUF + blk * W_BO, WL + p * WBUF + blk * W_BO,
                     cc, r, mbase, nbase);
        if (has) {
            int q = p ^ 1;
            stage_w(WH + q * WBUF, WL + q * WBUF, pw0, pw1, wk, wn8);
        }
        __syncthreads();
        p ^= 1;
    }

    // epilogue 2: dh (full fp32) -> Hc compact [k][m] stride 68; stage wu2
#pragma unroll
    for (int mt = 0; mt < 2; mt++) {
        int row = mbase + 16 * mt + r;
#pragma unroll
        for (int nt = 0; nt < 4; nt++) {
            int col = nbase + 8 * nt + 2 * cc;
            float b0 = bu1s[col], b1 = bu1s[col + 1];
            Hc[col * 68 + row]           = fmaxf(d[mt][nt][0] + b0, 0.0f);
            Hc[(col + 1) * 68 + row]     = fmaxf(d[mt][nt][1] + b1, 0.0f);
            Hc[col * 68 + row + 8]       = fmaxf(d[mt][nt][2] + b0, 0.0f);
            Hc[(col + 1) * 68 + row + 8] = fmaxf(d[mt][nt][3] + b1, 0.0f);
        }
    }
    {
        int f = tid * 8;   // 2048 floats
        *reinterpret_cast<float4*>(&wu2s[f])     = *reinterpret_cast<const float4*>(&wu2[f]);
        *reinterpret_cast<float4*>(&wu2s[f + 4]) = *reinterpret_cast<const float4*>(&wu2[f + 4]);
    }
    __syncthreads();

    // ---- phase 3: delta = dh @ wu2 + bu2; state += step*delta ----
    {
        int col = tid & 15;
        int rg  = tid >> 4;   // 0..15 -> rows rg*4..+3
        float acc[4] = {0.0f, 0.0f, 0.0f, 0.0f};
        for (int kk = 0; kk < 128; kk++) {
            float w = wu2s[kk * 16 + col];
            float4 a4 = *reinterpret_cast<const float4*>(&Hc[kk * 68 + rg * 4]);
            acc[0] += a4.x * w;
            acc[1] += a4.y * w;
            acc[2] += a4.z * w;
            acc[3] += a4.w * w;
        }
        float stp = sstep[0];
        float bv = bu2s[col];
#pragma unroll
        for (int i = 0; i < 4; i++) {
            int m = m0 + rg * 4 + i;
            state[(size_t)m * SD + col] += stp * (acc[i] + bv);
        }
    }
}

// ---------------- initial state build ----------------------------------------
__global__ void init_state_kernel(const float* __restrict__ sx,
                                  const float* __restrict__ sy,
                                  const float* __restrict__ doff) {
    int row = blockIdx.x * blockDim.x + threadIdx.x;
    if (row >= NROWS) return;
    int n = row % NP;
    const float* ini = g_init + (size_t)row * SD;
    float* st = g_state + (size_t)row * SD;
    st[0] = sx[n] + ini[0] * 0.15f;
    st[1] = sy[n] + ini[1] * 0.15f;
    st[2] = doff[0] + g_dep[row] * -2.0f;
#pragma unroll
    for (int i = 3; i < SD; i++) st[i] = ini[i];
}

// ---------------- fused kNN + pin gather (2 blocks per batch) ----------------
__global__ void __launch_bounds__(384) neighpin_kernel() {
    __shared__ float st[NP * SD];   // 24128 B
    int b = blockIdx.x >> 1;
    int half = blockIdx.x & 1;
    int t = threadIdx.x;

    const float4* gs = reinterpret_cast<const float4*>(g_state + (size_t)b * NP * SD);
    float4* s4 = reinterpret_cast<float4*>(st);
    for (int i = t; i < NP * SD / 4; i += 384) s4[i] = gs[i];
    __syncthreads();

    int pt = half * 189 + t;
    if (t >= 189 || pt >= NP) return;

    float bd[KNEI + 1];
    int bi[KNEI + 1];
#pragma unroll
    for (int i = 0; i <= KNEI; i++) { bd[i] = 3.4e38f; bi[i] = -1; }

    float x = st[pt * SD + 0], y = st[pt * SD + 1], z = st[pt * SD + 2];
    for (int j = 0; j < NP; j++) {
        float dx = x - st[j * SD + 0];
        float dy = y - st[j * SD + 1];
        float dz = z - st[j * SD + 2];
        float d2 = dx * dx + dy * dy + dz * dz;
        if (d2 < bd[KNEI]) {
            int p = KNEI;
            while (p > 0 && bd[p - 1] > d2) {
                bd[p] = bd[p - 1];
                bi[p] = bi[p - 1];
                p--;
            }
            bd[p] = d2;
            bi[p] = j;
        }
    }

    float4* p4 = reinterpret_cast<float4*>(g_pin + (size_t)(b * NP + pt) * PIN_DIM);
    const float4* self = reinterpret_cast<const float4*>(&st[pt * SD]);
#pragma unroll
    for (int q = 0; q < 4; q++) p4[q] = self[q];
#pragma unroll
    for (int k = 0; k < KNEI; k++) {
        const float4* nb = reinterpret_cast<const float4*>(&st[bi[k + 1] * SD]);
#pragma unroll
        for (int q = 0; q < 4; q++) p4[4 + k * 4 + q] = nb[q];
    }
}

// ---------------- postprocess ------------------------------------------------
__device__ __forceinline__ float sgnf(float x) {
    return (x > 0.0f) ? 1.0f : ((x < 0.0f) ? -1.0f : 0.0f);
}

__global__ void final_kernel(float* __restrict__ out) {
    int row = blockIdx.x * blockDim.x + threadIdx.x;
    if (row >= NROWS) return;
    const float* s = g_state + (size_t)row * SD;
    float o[14];
    o[0] = s[0]; o[1] = s[1]; o[2] = s[2];

#pragma unroll
    for (int i = 0; i < 3; i++) {
        float tv = fminf(fmaxf(s[3 + i], -10.0f), 20.0f) + 1.0f;
        float sp = log1pf(expf(tv));
        o[3 + i] = fminf(fmaxf(sp * 0.15f, 1e-6f), 2.0f);
    }

    const float eps = 1e-8f;
    float a1x = s[6], a1y = s[7], a1z = s[8];
    float a2x = s[9], a2y = s[10], a2z = s[11];
    float n1 = sqrtf(a1x * a1x + a1y * a1y + a1z * a1z) + eps;
    float b1x = a1x / n1, b1y = a1y / n1, b1z = a1z / n1;
    float dd = b1x * a2x + b1y * a2y + b1z * a2z;
    float pxv = a2x - dd * b1x, pyv = a2y - dd * b1y, pzv = a2z - dd * b1z;
    float n2 = sqrtf(pxv * pxv + pyv * pyv + pzv * pzv) + eps;
    float b2x = pxv / n2, b2y = pyv / n2, b2z = pzv / n2;
    float b3x = b1y * b2z - b1z * b2y;
    float b3y = b1z * b2x - b1x * b2z;
    float b3z = b1x * b2y - b1y * b2x;
    float m00 = b1x, m11 = b2y, m22 = b3z;
    float qw = 0.5f * sqrtf(fmaxf(1.0f + m00 + m11 + m22, 0.0f) + eps);
    float qx = 0.5f * sqrtf(fmaxf(1.0f + m00 - m11 - m22, 0.0f) + eps) * sgnf(b2z - b3y);
    float qy = 0.5f * sqrtf(fmaxf(1.0f - m00 + m11 - m22, 0.0f) + eps) * sgnf(b3x - b1z);
    float qz = 0.5f * sqrtf(fmaxf(1.0f - m00 - m11 + m22, 0.0f) + eps) * sgnf(b1y - b2x);
    float qn = sqrtf(qw * qw + qx * qx + qy * qy + qz * qz) + eps;
    o[6] = qw / qn; o[7] = qx / qn; o[8] = qy / qn; o[9] = qz / qn;

    o[10] = 1.0f / (1.0f + expf(-s[12]));
    o[11] = 1.0f / (1.0f + expf(-s[13]));
    o[12] = 1.0f / (1.0f + expf(-s[14]));
    o[13] = 1.0f / (1.0f + expf(-s[15]));

    float* op = out + (size_t)row * 14;
#pragma unroll
    for (int i = 0; i < 14; i++) op[i] = o[i];
}

// ---------------- launch ------------------------------------------------------
extern "C" void kernel_launch(void* const* d_in, const int* in_sizes, int n_in,
                              void* d_out, int out_size) {
    const float* feat  = (const float*)d_in[0];
    const float* depth = (const float*)d_in[1];
    const float* sx    = (const float*)d_in[2];
    const float* sy    = (const float*)d_in[3];
    const float* doff  = (const float*)d_in[4];
    const float* sstep = (const float*)d_in[5];
    const float* wi1 = (const float*)d_in[6];
    const float* bi1 = (const float*)d_in[7];
    const float* wi2 = (const float*)d_in[8];
    const float* bi2 = (const float*)d_in[9];
    const float* wi3 = (const float*)d_in[10];
    const float* bi3 = (const float*)d_in[11];
    const float* wp1 = (const float*)d_in[12];
    const float* bp1 = (const float*)d_in[13];
    const float* wp2 = (const float*)d_in[14];
    const float* bp2 = (const float*)d_in[15];
    const float* wu1 = (const float*)d_in[16];
    const float* bu1 = (const float*)d_in[17];
    const float* wu2 = (const float*)d_in[18];
    const float* bu2 = (const float*)d_in[19];

    cudaFuncSetAttribute(gemm_tc, cudaFuncAttributeMaxDynamicSharedMemorySize, G2_TOTAL_B);
    cudaFuncSetAttribute(fused_step, cudaFuncAttributeMaxDynamicSharedMemorySize, F2_TOTAL_B);

    void *pFs, *pA, *pB, *pInit, *pState, *pPin;
    cudaGetSymbolAddress(&pFs, g_Fs);
    cudaGetSymbolAddress(&pA, g_bufA);
    cudaGetSymbolAddress(&pB, g_bufB);
    cudaGetSymbolAddress(&pInit, g_init);
    cudaGetSymbolAddress(&pState, g_state);
    cudaGetSymbolAddress(&pPin, g_pin);
    float* Fs = (float*)pFs;
    float* bufA = (float*)pA;
    float* bufB = (float*)pB;
    float* initb = (float*)pInit;
    float* state = (float*)pState;
    float* pin = (float*)pPin;

    const int MB = NROWS / 64;  // 377

    // launches 0,1: sampling (launch #3 = gemm_tc wi2 for ncu)
    sample_feat_kernel<<<NROWS, 128>>>(feat, sx, sy);
    sample_depth_kernel<<<(NROWS + 127) / 128, 128>>>(depth, sx, sy);

    // launch 2: wi1 (K=384, N=256); launch 3: wi2 (K=256, N=128) <- profiled
    gemm_tc<<<dim3(MB, 2), 256, G2_TOTAL_B>>>(Fs, wi1, bi1, bufA, CIN, H2X);
    gemm_tc<<<dim3(MB, 1), 256, G2_TOTAL_B>>>(bufA, wi2, bi2, bufB, H2X, HID);
    gemm_kernel<64, 16, 16, 4, 1, 1><<<dim3(MB, 1), 256>>>(bufB, wi3, bi3, initb, HID, SD);

    init_state_kernel<<<(NROWS + 255) / 256, 256>>>(sx, sy, doff);

    for (int s = 0; s < NSTEPS; s++) {
        neighpin_kernel<<<BB * 2, 384>>>();
        gemm_tc<<<dim3(MB, 2), 256, G2_TOTAL_B>>>(pin, wp1, bp1, bufA, PIN_DIM, H2X);
        fused_step<<<MB, 256, F2_TOTAL_B>>>(bufA, wp2, bp2, wu1, bu1, wu2, bu2, sstep, state);
    }

    final_kernel<<<(NROWS + 255) / 256, 256>>>((float*)d_out);
}

// round 10
// speedup vs baseline: 1.3072x; 1.3072x over previous
#include <cuda_runtime.h>
#include <math.h>

// ---------------- problem constants ----------------
#define BB      64
#define NP      377
#define NROWS   (BB * NP)        // 24128 = 377 * 64
#define CIN     384
#define HID     128
#define H2X     256
#define SD      16
#define KNEI    6
#define PIN_DIM (SD * (KNEI + 1)) // 112
#define NSTEPS  16
#define FH      37
#define DHH     518
#define CCHUNK  8                // channels per sample_feat block

// fused_step dynamic smem layout (floats)
#define FS_AS_OFF   0                       // As[2][16][68]  = 2176
#define FS_WS_OFF   2176                    // Ws[2][16][128] = 4096
#define FS_HS_OFF   (2176 + 4096)           // Hs[128][68]    = 8704 (also reduce buf)
#define FS_B1_OFF   (FS_HS_OFF + 8704)      // bp2s[128]
#define FS_B2_OFF   (FS_B1_OFF + 128)       // bu1s[128]
#define FS_B3_OFF   (FS_B2_OFF + 128)       // bu2s[16]
#define FS_TOTAL_F  (FS_B3_OFF + 16)        // 15248 floats
#define FS_TOTAL_B  (FS_TOTAL_F * 4)        // 60992 bytes

typedef unsigned long long u64;

// ---- packed f32x2 helpers (sm_100a) -----------------------------------------
__device__ __forceinline__ u64 bcast2(float x) {
    u64 r;
    asm("mov.b64 %0, {%1, %1};" : "=l"(r) : "f"(x));
    return r;
}
__device__ __forceinline__ void fma2(u64& acc, u64 a, u64 w) {
    asm("fma.rn.f32x2 %0, %1, %2, %0;" : "+l"(acc) : "l"(a), "l"(w));
}
__device__ __forceinline__ void unpack2(u64 v, float& lo, float& hi) {
    asm("mov.b64 {%0, %1}, %2;" : "=f"(lo), "=f"(hi) : "l"(v));
}

// ---------------- scratch ----------------------------------------------------
__device__ float g_Fs[(size_t)NROWS * CIN];
__device__ float g_dep[NROWS];
__device__ float g_bufA[(size_t)NROWS * H2X];
__device__ float g_bufB[(size_t)NROWS * HID];
__device__ float g_init[(size_t)NROWS * SD];
__device__ float g_state[(size_t)NROWS * SD];
__device__ float g_pin[(size_t)NROWS * PIN_DIM];

// ---------------- feature bilinear sampling (smem-image, coalesced) ----------
__global__ void __launch_bounds__(256) sample_feat_kernel(
        const float* __restrict__ feat,
        const float* __restrict__ sx,
        const float* __restrict__ sy) {
    __shared__ float img[CCHUNK * FH * FH];   // 8 * 1369 floats = 43808 B

    int b  = blockIdx.x;
    int c0 = blockIdx.y * CCHUNK;

    // stream 8 channel images into smem (fully coalesced)
    const float* src = feat + ((size_t)b * CIN + c0) * FH * FH;
    for (int i = threadIdx.x; i < CCHUNK * FH * FH; i += 256) img[i] = src[i];
    __syncthreads();

    // work item = (point n, channel cc)
    for (int it = threadIdx.x; it < NP * CCHUNK; it += 256) {
        int n = it >> 3, cc = it & 7;
        float gx = sx[n], gy = sy[n];
        float ix = fminf(fmaxf((gx + 1.0f) * 0.5f * (float)(FH - 1), 0.0f), (float)(FH - 1));
        float iy = fminf(fmaxf((gy + 1.0f) * 0.5f * (float)(FH - 1), 0.0f), (float)(FH - 1));
        int x0 = (int)floorf(ix), y0 = (int)floorf(iy);
        int x1 = min(x0 + 1, FH - 1), y1 = min(y0 + 1, FH - 1);
        float wx = ix - (float)x0, wy = iy - (float)y0;
        float w00 = (1.0f - wx) * (1.0f - wy);
        float w01 = wx * (1.0f - wy);
        float w10 = (1.0f - wx) * wy;
        float w11 = wx * wy;

        const float* p = img + cc * FH * FH;
        float v = p[y0 * FH + x0] * w00 + p[y0 * FH + x1] * w01 +
                  p[y1 * FH + x0] * w10 + p[y1 * FH + x1] * w11;
        g_Fs[((size_t)b * NP + n) * CIN + c0 + cc] = v;
    }
}

// ---------------- depth bilinear sampling ------------------------------------
__global__ void sample_depth_kernel(const float* __restrict__ depth,
                                    const float* __restrict__ sx,
                                    const float* __restrict__ sy) {
    int row = blockIdx.x * blockDim.x + threadIdx.x;
    if (row >= NROWS) return;
    int b = row / NP, n = row % NP;
    float gx = sx[n], gy = sy[n];
    float jx = fminf(fmaxf((gx + 1.0f) * 0.5f * (float)(DHH - 1), 0.0f), (float)(DHH - 1));
    float jy = fminf(fmaxf((gy + 1.0f) * 0.5f * (float)(DHH - 1), 0.0f), (float)(DHH - 1));
    int a0 = (int)floorf(jx), c0 = (int)floorf(jy);
    int a1 = min(a0 + 1, DHH - 1), c1 = min(c0 + 1, DHH - 1);
    float ux = jx - (float)a0, uy = jy - (float)c0;
    const float* dp = depth + (size_t)b * DHH * DHH;
    float v = dp[c0 * DHH + a0] * (1.0f - ux) * (1.0f - uy) +
              dp[c0 * DHH + a1] * ux * (1.0f - uy) +
              dp[c1 * DHH + a0] * (1.0f - ux) * uy +
              dp[c1 * DHH + a1] * ux * uy;
    g_dep[row] = v;
}

// ---- 8-deep k micro-kernel, 8x8 tile, packed --------------------------------
__device__ __forceinline__ void mma_tile8(
    u64 acc64[8][4], const float (*As8)[68], const float (*Ws8)[128],
    int r8, int c16) {
#pragma unroll
    for (int kk = 0; kk < 8; kk++) {
        float4 a0 = *reinterpret_cast<const float4*>(&As8[kk][r8 * 4]);
        float4 a1 = *reinterpret_cast<const float4*>(&As8[kk][32 + r8 * 4]);
        ulonglong2 wva = *reinterpret_cast<const ulonglong2*>(&Ws8[kk][c16 * 8]);
        ulonglong2 wvb = *reinterpret_cast<const ulonglong2*>(&Ws8[kk][c16 * 8 + 4]);
        u64 wpk[4] = {wva.x, wva.y, wvb.x, wvb.y};
        u64 ab[8] = {bcast2(a0.x), bcast2(a0.y), bcast2(a0.z), bcast2(a0.w),
                     bcast2(a1.x), bcast2(a1.y), bcast2(a1.z), bcast2(a1.w)};
#pragma unroll
        for (int i = 0; i < 8; i++)
#pragma unroll
            for (int j = 0; j < 4; j++) fma2(acc64[i][j], ab[i], wpk[j]);
    }
}

// ---- group-1 -> group-0 reduction of acc rows [r*4, r*4+4) via red buffer ---
__device__ __forceinline__ void red_store(float* red, u64 acc64[8][4], int r, int wt) {
#pragma unroll
    for (int i = 0; i < 4; i++)
#pragma unroll
        for (int j = 0; j < 4; j++) {
            float lo, hi;
            unpack2(acc64[r * 4 + i][j], lo, hi);
            red[(i * 8 + 2 * j) * 128 + wt] = lo;
            red[(i * 8 + 2 * j + 1) * 128 + wt] = hi;
        }
}
__device__ __forceinline__ void red_add(const float* red, float accf[8][8], int r, int wt) {
#pragma unroll
    for (int i = 0; i < 4; i++)
#pragma unroll
        for (int j2 = 0; j2 < 8; j2++)
            accf[r * 4 + i][j2] += red[(i * 8 + j2) * 128 + wt];
}

// ---------------- 64x128 GEMM, 256 thr, K-split warp groups, 8x8 tile --------
template <int EPI>
__global__ void __launch_bounds__(256, 2)
gemm64x128(const float* __restrict__ A, const float* __restrict__ W,
           const float* __restrict__ bias, float* __restrict__ C,
           int K, int N) {
    __shared__ float As[2][16][68];
    __shared__ float Ws[2][16][128];

    int m0 = blockIdx.x * 64;
    int n0 = blockIdx.y * 128;
    int tid = threadIdx.x;
    int g   = tid >> 7;            // warp group: kk range [g*8, g*8+8)
    int wt  = tid & 127;
    int r8 = wt & 7, c16 = wt >> 3;

    int am = tid >> 2;             // 0..63 (A staging, 256 thr)
    int aq = (tid & 3) * 4;
    int wk = tid >> 5;             // 0..7
    int wn = (tid & 31) * 4;

    u64 acc64[8][4];
#pragma unroll
    for (int i = 0; i < 8; i++)
#pragma unroll
        for (int j = 0; j < 4; j++) acc64[i][j] = 0ull;

    // preload tile 0
    {
        float4 v = *reinterpret_cast<const float4*>(&A[(size_t)(m0 + am) * K + aq]);
        As[0][aq + 0][am] = v.x;
        As[0][aq + 1][am] = v.y;
        As[0][aq + 2][am] = v.z;
        As[0][aq + 3][am] = v.w;
    }
#pragma unroll
    for (int i = 0; i < 2; i++) {
        int k = wk + i * 8;
        *reinterpret_cast<float4*>(&Ws[0][k][wn]) =
            *reinterpret_cast<const float4*>(&W[(size_t)k * N + n0 + wn]);
    }
    __syncthreads();

    int KT = K >> 4;
    int p = 0;
    for (int t = 0; t < KT; t++) {
        float4 pa, pw[2];
        bool has = (t + 1 < KT);
        if (has) {
            int k0 = (t + 1) << 4;
            pa = *reinterpret_cast<const float4*>(&A[(size_t)(m0 + am) * K + k0 + aq]);
#pragma unroll
            for (int i = 0; i < 2; i++)
                pw[i] = *reinterpret_cast<const float4*>(
                    &W[(size_t)(k0 + wk + i * 8) * N + n0 + wn]);
        }

        mma_tile8(acc64,
                  reinterpret_cast<const float (*)[68]>(&As[p][g * 8][0]),
                  reinterpret_cast<const float (*)[128]>(&Ws[p][g * 8][0]),
                  r8, c16);

        if (has) {
            int q = p ^ 1;
            As[q][aq + 0][am] = pa.x;
            As[q][aq + 1][am] = pa.y;
            As[q][aq + 2][am] = pa.z;
            As[q][aq + 3][am] = pa.w;
#pragma unroll
            for (int i = 0; i < 2; i++)
                *reinterpret_cast<float4*>(&Ws[q][wk + i * 8][wn]) = pw[i];
        }
        __syncthreads();
        p ^= 1;
    }

    // ---- cross-group reduction (red buffer aliases Ws: 4096 floats) ----
    float* red = &Ws[0][0][0];
    float accf[8][8];
    if (g == 0) {
#pragma unroll
        for (int i = 0; i < 8; i++)
#pragma unroll
            for (int j = 0; j < 4; j++) unpack2(acc64[i][j], accf[i][2 * j], accf[i][2 * j + 1]);
    }
#pragma unroll
    for (int r = 0; r < 2; r++) {
        if (g == 1) red_store(red, acc64, r, wt);
        __syncthreads();
        if (g == 0) red_add(red, accf, r, wt);
        __syncthreads();
    }

    if (g == 0) {
        float bb[8];
#pragma unroll
        for (int j = 0; j < 8; j++) bb[j] = bias[n0 + c16 * 8 + j];
#pragma unroll
        for (int h = 0; h < 2; h++) {
#pragma unroll
            for (int i = 0; i < 4; i++) {
                int m = m0 + h * 32 + r8 * 4 + i;
                int ai = h * 4 + i;
                float v[8];
#pragma unroll
                for (int j = 0; j < 8; j++) {
                    v[j] = accf[ai][j] + bb[j];
                    if (EPI == 0) v[j] = fmaxf(v[j], 0.0f);
                }
                float4* cp = reinterpret_cast<float4*>(&C[(size_t)m * N + n0 + c16 * 8]);
                cp[0] = make_float4(v[0], v[1], v[2], v[3]);
                cp[1] = make_float4(v[4], v[5], v[6], v[7]);
            }
        }
    }
}

// ---------------- small GEMM (N=16), used once for wi3 -----------------------
template <int BM, int BN, int BK, int TM, int TN, int EPI>
__global__ void gemm_kernel(const float* __restrict__ A,
                            const float* __restrict__ W,
                            const float* __restrict__ bias,
                            float* __restrict__ C,
                            int K, int N) {
    constexpr int TX = BN / TN;
    constexpr int TY = BM / TM;
    static_assert(TX * TY == 256, "256 threads");
    constexpr int AS = BM + 4;
    __shared__ float As[BK][AS];
    __shared__ float Ws[BK][BN];

    int m0 = blockIdx.x * BM;
    int n0 = blockIdx.y * BN;
    int tid = threadIdx.x;
    int tx = tid % TX, ty = tid / TX;

    float acc[TM][TN];
#pragma unroll
    for (int i = 0; i < TM; i++)
#pragma unroll
        for (int j = 0; j < TN; j++) acc[i][j] = 0.0f;

    int am = tid >> 2;
    int aq = (tid & 3) * 4;

    for (int k0 = 0; k0 < K; k0 += BK) {
        {
            const float4 v = *reinterpret_cast<const float4*>(
                &A[(size_t)(m0 + am) * K + k0 + aq]);
            As[aq + 0][am] = v.x;
            As[aq + 1][am] = v.y;
            As[aq + 2][am] = v.z;
            As[aq + 3][am] = v.w;
        }
        for (int i = tid; i < BK * BN; i += 256) {
            int k = i / BN, n = i % BN;
            Ws[k][n] = W[(size_t)(k0 + k) * N + n0 + n];
        }
        __syncthreads();
#pragma unroll
        for (int kk = 0; kk < BK; kk++) {
            float a[TM], w[TN];
#pragma unroll
            for (int i = 0; i < TM; i++) a[i] = As[kk][ty * TM + i];
#pragma unroll
            for (int j = 0; j < TN; j++) w[j] = Ws[kk][tx * TN + j];
#pragma unroll
            for (int i = 0; i < TM; i++)
#pragma unroll
                for (int j = 0; j < TN; j++) acc[i][j] += a[i] * w[j];
        }
        __syncthreads();
    }
#pragma unroll
    for (int i = 0; i < TM; i++) {
        int m = m0 + ty * TM + i;
#pragma unroll
        for (int j = 0; j < TN; j++) {
            int n = n0 + tx * TN + j;
            float v = acc[i][j] + bias[n];
            if (EPI == 0) v = fmaxf(v, 0.0f);
            C[(size_t)m * N + n] = v;
        }
    }
}

// ---------------- fused wp2 -> wu1 -> wu2 -> state update --------------------
// 256 threads, K-split warp groups in phases 1-2; phase 3 all threads.
__global__ void __launch_bounds__(256, 2)
fused_step(const float* __restrict__ A,           // g_bufA (h1), row len 256
           const float* __restrict__ wp2, const float* __restrict__ bp2,
           const float* __restrict__ wu1, const float* __restrict__ bu1,
           const float* __restrict__ wu2, const float* __restrict__ bu2,
           const float* __restrict__ sstep,
           float* __restrict__ state) {
    extern __shared__ float dyn[];
    float (*As)[16][68]  = reinterpret_cast<float (*)[16][68]>(dyn + FS_AS_OFF);
    float (*Ws)[16][128] = reinterpret_cast<float (*)[16][128]>(dyn + FS_WS_OFF);
    float (*Hs)[68]      = reinterpret_cast<float (*)[68]>(dyn + FS_HS_OFF);
    float* redH = dyn + FS_HS_OFF;   // 8192 floats of Hs area as reduce buf
    float* bp2s = dyn + FS_B1_OFF;
    float* bu1s = dyn + FS_B2_OFF;
    float* bu2s = dyn + FS_B3_OFF;

    int m0 = blockIdx.x * 64;
    int tid = threadIdx.x;
    int g   = tid >> 7;
    int wt  = tid & 127;
    int r8 = wt & 7, c16 = wt >> 3;
    int am = tid >> 2;
    int aq = (tid & 3) * 4;
    int wk = tid >> 5;
    int wn = (tid & 31) * 4;

    if (tid < 128) { bp2s[tid] = bp2[tid]; bu1s[tid] = bu1[tid]; }
    if (tid < 16)  { bu2s[tid] = bu2[tid]; }

    u64 acc64[8][4];
#pragma unroll
    for (int i = 0; i < 8; i++)
#pragma unroll
        for (int j = 0; j < 4; j++) acc64[i][j] = 0ull;

    // ---- phase 1: h2 = relu(h1 @ wp2 + bp2), K=256 ----
    {
        float4 v = *reinterpret_cast<const float4*>(&A[(size_t)(m0 + am) * 256 + aq]);
        As[0][aq + 0][am] = v.x;
        As[0][aq + 1][am] = v.y;
        As[0][aq + 2][am] = v.z;
        As[0][aq + 3][am] = v.w;
    }
#pragma unroll
    for (int i = 0; i < 2; i++) {
        int k = wk + i * 8;
        *reinterpret_cast<float4*>(&Ws[0][k][wn]) =
            *reinterpret_cast<const float4*>(&wp2[(size_t)k * 128 + wn]);
    }
    __syncthreads();

    int p = 0;
    for (int t = 0; t < 16; t++) {
        float4 pa, pw[2];
        bool has = (t + 1 < 16);
        if (has) {
            int k0 = (t + 1) << 4;
            pa = *reinterpret_cast<const float4*>(&A[(size_t)(m0 + am) * 256 + k0 + aq]);
#pragma unroll
            for (int i = 0; i < 2; i++)
                pw[i] = *reinterpret_cast<const float4*>(
                    &wp2[(size_t)(k0 + wk + i * 8) * 128 + wn]);
        }
        mma_tile8(acc64,
                  reinterpret_cast<const float (*)[68]>(&As[p][g * 8][0]),
                  reinterpret_cast<const float (*)[128]>(&Ws[p][g * 8][0]),
                  r8, c16);
        if (has) {
            int q = p ^ 1;
            As[q][aq + 0][am] = pa.x;
            As[q][aq + 1][am] = pa.y;
            As[q][aq + 2][am] = pa.z;
            As[q][aq + 3][am] = pa.w;
#pragma unroll
            for (int i = 0; i < 2; i++)
                *reinterpret_cast<float4*>(&Ws[q][wk + i * 8][wn]) = pw[i];
        }
        __syncthreads();
        p ^= 1;
    }

    // reduction (redH = Hs area) + h2 store
    {
        float accf[8][8];
        if (g == 0) {
#pragma unroll
            for (int i = 0; i < 8; i++)
#pragma unroll
                for (int j = 0; j < 4; j++) unpack2(acc64[i][j], accf[i][2 * j], accf[i][2 * j + 1]);
        }
#pragma unroll
        for (int r = 0; r < 2; r++) {
            if (g == 1) red_store(redH, acc64, r, wt);
            __syncthreads();
            if (g == 0) red_add(redH, accf, r, wt);
            __syncthreads();
        }
        if (g == 0) {
#pragma unroll
            for (int j = 0; j < 8; j++) {
                int n = c16 * 8 + j;
                float v0[4], v1[4];
#pragma unroll
                for (int i = 0; i < 4; i++) v0[i] = fmaxf(accf[i][j] + bp2s[n], 0.0f);
#pragma unroll
                for (int i = 0; i < 4; i++) v1[i] = fmaxf(accf[4 + i][j] + bp2s[n], 0.0f);
                *reinterpret_cast<float4*>(&Hs[n][r8 * 4])      = make_float4(v0[0], v0[1], v0[2], v0[3]);
                *reinterpret_cast<float4*>(&Hs[n][32 + r8 * 4]) = make_float4(v1[0], v1[1], v1[2], v1[3]);
            }
        }
#pragma unroll
        for (int i = 0; i < 2; i++) {
            int k = wk + i * 8;
            *reinterpret_cast<float4*>(&Ws[0][k][wn]) =
                *reinterpret_cast<const float4*>(&wu1[(size_t)k * 128 + wn]);
        }
        __syncthreads();
    }

    // ---- phase 2: dh = relu(h2 @ wu1 + bu1), K=128, A in Hs ----
#pragma unroll
    for (int i = 0; i < 8; i++)
#pragma unroll
        for (int j = 0; j < 4; j++) acc64[i][j] = 0ull;

    p = 0;
    for (int c = 0; c < 8; c++) {
        float4 pw[2];
        bool has = (c + 1 < 8);
        if (has) {
            int k0 = (c + 1) << 4;
#pragma unroll
            for (int i = 0; i < 2; i++)
                pw[i] = *reinterpret_cast<const float4*>(
                    &wu1[(size_t)(k0 + wk + i * 8) * 128 + wn]);
        }
        mma_tile8(acc64,
                  reinterpret_cast<const float (*)[68]>(&Hs[c * 16 + g * 8][0]),
                  reinterpret_cast<const float (*)[128]>(&Ws[p][g * 8][0]),
                  r8, c16);
        if (has) {
            int q = p ^ 1;
#pragma unroll
            for (int i = 0; i < 2; i++)
                *reinterpret_cast<float4*>(&Ws[q][wk + i * 8][wn]) = pw[i];
        }
        __syncthreads();
        p ^= 1;
    }

    // reduction (redH) + dh store + wu2 staging
    {
        float accf[8][8];
        if (g == 0) {
#pragma unroll
            for (int i = 0; i < 8; i++)
#pragma unroll
                for (int j = 0; j < 4; j++) unpack2(acc64[i][j], accf[i][2 * j], accf[i][2 * j + 1]);
        }
#pragma unroll
        for (int r = 0; r < 2; r++) {
            if (g == 1) red_store(redH, acc64, r, wt);
            __syncthreads();
            if (g == 0) red_add(redH, accf, r, wt);
            __syncthreads();
        }
        if (g == 0) {
#pragma unroll
            for (int j = 0; j < 8; j++) {
                int n = c16 * 8 + j;
                float v0[4], v1[4];
#pragma unroll
                for (int i = 0; i < 4; i++) v0[i] = fmaxf(accf[i][j] + bu1s[n], 0.0f);
#pragma unroll
                for (int i = 0; i < 4; i++) v1[i] = fmaxf(accf[4 + i][j] + bu1s[n], 0.0f);
                *reinterpret_cast<float4*>(&Hs[n][r8 * 4])      = make_float4(v0[0], v0[1], v0[2], v0[3]);
                *reinterpret_cast<float4*>(&Hs[n][32 + r8 * 4]) = make_float4(v1[0], v1[1], v1[2], v1[3]);
            }
        }
        {
            float* wflat = &Ws[0][0][0];
#pragma unroll
            for (int i = 0; i < 2; i++) {
                int f = (tid + i * 256) * 4;   // 2048 floats
                *reinterpret_cast<float4*>(&wflat[f]) =
                    *reinterpret_cast<const float4*>(&wu2[f]);
            }
        }
        __syncthreads();
    }

    // ---- phase 3: delta = dh @ wu2 + bu2; state += step*delta ----
    {
        const float* wflat = &Ws[0][0][0];
        int col = tid & 15;
        int rg  = tid >> 4;   // 0..15 -> rows rg*4..+3
        float acc3[4];
#pragma unroll
        for (int i = 0; i < 4; i++) acc3[i] = 0.0f;
        for (int kk = 0; kk < 128; kk++) {
            float w = wflat[kk * 16 + col];
            float4 a4 = *reinterpret_cast<const float4*>(&Hs[kk][rg * 4]);
            acc3[0] += a4.x * w; acc3[1] += a4.y * w;
            acc3[2] += a4.z * w; acc3[3] += a4.w * w;
        }
        float stp = sstep[0];
        float bv = bu2s[col];
#pragma unroll
        for (int i = 0; i < 4; i++) {
            int m = m0 + rg * 4 + i;
            state[(size_t)m * SD + col] += stp * (acc3[i] + bv);
        }
    }
}

// ---------------- initial state build ----------------------------------------
__global__ void init_state_kernel(const float* __restrict__ sx,
                                  const float* __restrict__ sy,
                                  const float* __restrict__ doff) {
    int row = blockIdx.x * blockDim.x + threadIdx.x;
    if (row >= NROWS) return;
    int n = row % NP;
    const float* ini = g_init + (size_t)row * SD;
    float* st = g_state + (size_t)row * SD;
    st[0] = sx[n] + ini[0] * 0.15f;
    st[1] = sy[n] + ini[1] * 0.15f;
    st[2] = doff[0] + g_dep[row] * -2.0f;
#pragma unroll
    for (int i = 3; i < SD; i++) st[i] = ini[i];
}

// ---------------- fused kNN + pin gather (2 blocks per batch) ----------------
__global__ void __launch_bounds__(384) neighpin_kernel() {
    __shared__ float st[NP * SD];   // 24128 B
    int b = blockIdx.x >> 1;
    int half = blockIdx.x & 1;
    int t = threadIdx.x;

    const float4* gs = reinterpret_cast<const float4*>(g_state + (size_t)b * NP * SD);
    float4* s4 = reinterpret_cast<float4*>(st);
    for (int i = t; i < NP * SD / 4; i += 384) s4[i] = gs[i];
    __syncthreads();

    int pt = half * 189 + t;
    if (t >= 189 || pt >= NP) return;

    float bd[KNEI + 1];
    int bi[KNEI + 1];
#pragma unroll
    for (int i = 0; i <= KNEI; i++) { bd[i] = 3.4e38f; bi[i] = -1; }

    float x = st[pt * SD + 0], y = st[pt * SD + 1], z = st[pt * SD + 2];
    for (int j = 0; j < NP; j++) {
        float dx = x - st[j * SD + 0];
        float dy = y - st[j * SD + 1];
        float dz = z - st[j * SD + 2];
        float d2 = dx * dx + dy * dy + dz * dz;
        if (d2 < bd[KNEI]) {
            int p = KNEI;
            while (p > 0 && bd[p - 1] > d2) {
                bd[p] = bd[p - 1];
                bi[p] = bi[p - 1];
                p--;
            }
            bd[p] = d2;
            bi[p] = j;
        }
    }

    float4* p4 = reinterpret_cast<float4*>(g_pin + (size_t)(b * NP + pt) * PIN_DIM);
    const float4* self = reinterpret_cast<const float4*>(&st[pt * SD]);
#pragma unroll
    for (int q = 0; q < 4; q++) p4[q] = self[q];
#pragma unroll
    for (int k = 0; k < KNEI; k++) {
        const float4* nb = reinterpret_cast<const float4*>(&st[bi[k + 1] * SD]);
#pragma unroll
        for (int q = 0; q < 4; q++) p4[4 + k * 4 + q] = nb[q];
    }
}

// ---------------- postprocess ------------------------------------------------
__device__ __forceinline__ float sgnf(float x) {
    return (x > 0.0f) ? 1.0f : ((x < 0.0f) ? -1.0f : 0.0f);
}

__global__ void final_kernel(float* __restrict__ out) {
    int row = blockIdx.x * blockDim.x + threadIdx.x;
    if (row >= NROWS) return;
    const float* s = g_state + (size_t)row * SD;
    float o[14];
    o[0] = s[0]; o[1] = s[1]; o[2] = s[2];

#pragma unroll
    for (int i = 0; i < 3; i++) {
        float tv = fminf(fmaxf(s[3 + i], -10.0f), 20.0f) + 1.0f;
        float sp = log1pf(expf(tv));
        o[3 + i] = fminf(fmaxf(sp * 0.15f, 1e-6f), 2.0f);
    }

    const float eps = 1e-8f;
    float a1x = s[6], a1y = s[7], a1z = s[8];
    float a2x = s[9], a2y = s[10], a2z = s[11];
    float n1 = sqrtf(a1x * a1x + a1y * a1y + a1z * a1z) + eps;
    float b1x = a1x / n1, b1y = a1y / n1, b1z = a1z / n1;
    float dd = b1x * a2x + b1y * a2y + b1z * a2z;
    float pxv = a2x - dd * b1x, pyv = a2y - dd * b1y, pzv = a2z - dd * b1z;
    float n2 = sqrtf(pxv * pxv + pyv * pyv + pzv * pzv) + eps;
    float b2x = pxv / n2, b2y = pyv / n2, b2z = pzv / n2;
    float b3x = b1y * b2z - b1z * b2y;
    float b3y = b1z * b2x - b1x * b2z;
    float b3z = b1x * b2y - b1y * b2x;
    float m00 = b1x, m11 = b2y, m22 = b3z;
    float qw = 0.5f * sqrtf(fmaxf(1.0f + m00 + m11 + m22, 0.0f) + eps);
    float qx = 0.5f * sqrtf(fmaxf(1.0f + m00 - m11 - m22, 0.0f) + eps) * sgnf(b2z - b3y);
    float qy = 0.5f * sqrtf(fmaxf(1.0f - m00 + m11 - m22, 0.0f) + eps) * sgnf(b3x - b1z);
    float qz = 0.5f * sqrtf(fmaxf(1.0f - m00 - m11 + m22, 0.0f) + eps) * sgnf(b1y - b2x);
    float qn = sqrtf(qw * qw + qx * qx + qy * qy + qz * qz) + eps;
    o[6] = qw / qn; o[7] = qx / qn; o[8] = qy / qn; o[9] = qz / qn;

    o[10] = 1.0f / (1.0f + expf(-s[12]));
    o[11] = 1.0f / (1.0f + expf(-s[13]));
    o[12] = 1.0f / (1.0f + expf(-s[14]));
    o[13] = 1.0f / (1.0f + expf(-s[15]));

    float* op = out + (size_t)row * 14;
#pragma unroll
    for (int i = 0; i < 14; i++) op[i] = o[i];
}

// ---------------- launch ------------------------------------------------------
extern "C" void kernel_launch(void* const* d_in, const int* in_sizes, int n_in,
                              void* d_out, int out_size) {
    const float* feat  = (const float*)d_in[0];
    const float* depth = (const float*)d_in[1];
    const float* sx    = (const float*)d_in[2];
    const float* sy    = (const float*)d_in[3];
    const float* doff  = (const float*)d_in[4];
    const float* sstep = (const float*)d_in[5];
    const float* wi1 = (const float*)d_in[6];
    const float* bi1 = (const float*)d_in[7];
    const float* wi2 = (const float*)d_in[8];
    const float* bi2 = (const float*)d_in[9];
    const float* wi3 = (const float*)d_in[10];
    const float* bi3 = (const float*)d_in[11];
    const float* wp1 = (const float*)d_in[12];
    const float* bp1 = (const float*)d_in[13];
    const float* wp2 = (const float*)d_in[14];
    const float* bp2 = (const float*)d_in[15];
    const float* wu1 = (const float*)d_in[16];
    const float* bu1 = (const float*)d_in[17];
    const float* wu2 = (const float*)d_in[18];
    const float* bu2 = (const float*)d_in[19];

    cudaFuncSetAttribute(fused_step, cudaFuncAttributeMaxDynamicSharedMemorySize,
                         FS_TOTAL_B);

    void *pFs, *pA, *pB, *pInit, *pState, *pPin;
    cudaGetSymbolAddress(&pFs, g_Fs);
    cudaGetSymbolAddress(&pA, g_bufA);
    cudaGetSymbolAddress(&pB, g_bufB);
    cudaGetSymbolAddress(&pInit, g_init);
    cudaGetSymbolAddress(&pState, g_state);
    cudaGetSymbolAddress(&pPin, g_pin);
    float* Fs = (float*)pFs;
    float* bufA = (float*)pA;
    float* bufB = (float*)pB;
    float* initb = (float*)pInit;
    float* state = (float*)pState;
    float* pin = (float*)pPin;

    const int MB = NROWS / 64;  // 377

    // launches 0,1: sampling (launch #3 = gemm64x128 for ncu)
    sample_feat_kernel<<<dim3(BB, CIN / CCHUNK), 256>>>(feat, sx, sy);
    sample_depth_kernel<<<(NROWS + 127) / 128, 128>>>(depth, sx, sy);

    // launch 2: wi1 (K=384, N=256); launch 3: wi2 (K=256, N=128) <- profiled
    gemm64x128<0><<<dim3(MB, 2), 256>>>(Fs, wi1, bi1, bufA, CIN, H2X);
    gemm64x128<0><<<dim3(MB, 1), 256>>>(bufA, wi2, bi2, bufB, H2X, HID);
    gemm_kernel<64, 16, 16, 4, 1, 1><<<dim3(MB, 1), 256>>>(bufB, wi3, bi3, initb, HID, SD);

    init_state_kernel<<<(NROWS + 255) / 256, 256>>>(sx, sy, doff);

    for (int s = 0; s < NSTEPS; s++) {
        neighpin_kernel<<<BB * 2, 384>>>();
        gemm64x128<0><<<dim3(MB, 2), 256>>>(pin, wp1, bp1, bufA, PIN_DIM, H2X);
        fused_step<<<MB, 256, FS_TOTAL_B>>>(bufA, wp2, bp2, wu1, bu1, wu2, bu2, sstep, state);
    }

    final_kernel<<<(NROWS + 255) / 256, 256>>>((float*)d_out);
}

// round 11
// speedup vs baseline: 1.3175x; 1.0079x over previous
#include <cuda_runtime.h>
#include <math.h>
#include <stdint.h>

// ---------------- problem constants ----------------
#define BB      64
#define NP      377
#define NROWS   (BB * NP)        // 24128 = 377 * 64
#define CIN     384
#define HID     128
#define H2X     256
#define SD      16
#define KNEI    6
#define PIN_DIM (SD * (KNEI + 1)) // 112
#define NSTEPS  16
#define FH      37
#define DHH     518
#define CCHUNK  8                // channels per sample_feat block

// fused_step dynamic smem layout (floats)
#define FS_AS_OFF   0                       // As[2][16][68]  = 2176
#define FS_WS_OFF   2176                    // Ws[2][16][128] = 4096
#define FS_HS_OFF   (2176 + 4096)           // Hs[128][68]    = 8704 (also reduce buf)
#define FS_B1_OFF   (FS_HS_OFF + 8704)      // bp2s[128]
#define FS_B2_OFF   (FS_B1_OFF + 128)       // bu1s[128]
#define FS_B3_OFF   (FS_B2_OFF + 128)       // bu2s[16]
#define FS_TOTAL_F  (FS_B3_OFF + 16)        // 15248 floats
#define FS_TOTAL_B  (FS_TOTAL_F * 4)        // 60992 bytes

typedef unsigned long long u64;

// ---- packed f32x2 helpers (sm_100a) -----------------------------------------
__device__ __forceinline__ u64 bcast2(float x) {
    u64 r;
    asm("mov.b64 %0, {%1, %1};" : "=l"(r) : "f"(x));
    return r;
}
__device__ __forceinline__ void fma2(u64& acc, u64 a, u64 w) {
    asm("fma.rn.f32x2 %0, %1, %2, %0;" : "+l"(acc) : "l"(a), "l"(w));
}
__device__ __forceinline__ void unpack2(u64 v, float& lo, float& hi) {
    asm("mov.b64 {%0, %1}, %2;" : "=f"(lo), "=f"(hi) : "l"(v));
}

// ---- cp.async helpers --------------------------------------------------------
__device__ __forceinline__ void cp16(void* dst_smem, const void* src_gmem) {
    uint32_t d = (uint32_t)__cvta_generic_to_shared(dst_smem);
    asm volatile("cp.async.cg.shared.global [%0], [%1], 16;" :: "r"(d), "l"(src_gmem));
}
__device__ __forceinline__ void cp_commit() {
    asm volatile("cp.async.commit_group;");
}
__device__ __forceinline__ void cp_wait0() {
    asm volatile("cp.async.wait_group 0;" ::: "memory");
}

// ---------------- scratch ----------------------------------------------------
__device__ float g_Fs[(size_t)NROWS * CIN];
__device__ float g_dep[NROWS];
__device__ float g_bufA[(size_t)NROWS * H2X];
__device__ float g_bufB[(size_t)NROWS * HID];
__device__ float g_init[(size_t)NROWS * SD];
__device__ float g_state[(size_t)NROWS * SD];
__device__ float g_pin[(size_t)NROWS * PIN_DIM];

// ---------------- feature bilinear sampling (smem-image, coalesced) ----------
__global__ void __launch_bounds__(256) sample_feat_kernel(
        const float* __restrict__ feat,
        const float* __restrict__ sx,
        const float* __restrict__ sy) {
    __shared__ float img[CCHUNK * FH * FH];   // 8 * 1369 floats = 43808 B

    int b  = blockIdx.x;
    int c0 = blockIdx.y * CCHUNK;

    const float* src = feat + ((size_t)b * CIN + c0) * FH * FH;
    for (int i = threadIdx.x; i < CCHUNK * FH * FH; i += 256) img[i] = src[i];
    __syncthreads();

    for (int it = threadIdx.x; it < NP * CCHUNK; it += 256) {
        int n = it >> 3, cc = it & 7;
        float gx = sx[n], gy = sy[n];
        float ix = fminf(fmaxf((gx + 1.0f) * 0.5f * (float)(FH - 1), 0.0f), (float)(FH - 1));
        float iy = fminf(fmaxf((gy + 1.0f) * 0.5f * (float)(FH - 1), 0.0f), (float)(FH - 1));
        int x0 = (int)floorf(ix), y0 = (int)floorf(iy);
        int x1 = min(x0 + 1, FH - 1), y1 = min(y0 + 1, FH - 1);
        float wx = ix - (float)x0, wy = iy - (float)y0;
        float w00 = (1.0f - wx) * (1.0f - wy);
        float w01 = wx * (1.0f - wy);
        float w10 = (1.0f - wx) * wy;
        float w11 = wx * wy;

        const float* p = img + cc * FH * FH;
        float v = p[y0 * FH + x0] * w00 + p[y0 * FH + x1] * w01 +
                  p[y1 * FH + x0] * w10 + p[y1 * FH + x1] * w11;
        g_Fs[((size_t)b * NP + n) * CIN + c0 + cc] = v;
    }
}

// ---------------- depth bilinear sampling ------------------------------------
__global__ void sample_depth_kernel(const float* __restrict__ depth,
                                    const float* __restrict__ sx,
                                    const float* __restrict__ sy) {
    int row = blockIdx.x * blockDim.x + threadIdx.x;
    if (row >= NROWS) return;
    int b = row / NP, n = row % NP;
    float gx = sx[n], gy = sy[n];
    float jx = fminf(fmaxf((gx + 1.0f) * 0.5f * (float)(DHH - 1), 0.0f), (float)(DHH - 1));
    float jy = fminf(fmaxf((gy + 1.0f) * 0.5f * (float)(DHH - 1), 0.0f), (float)(DHH - 1));
    int a0 = (int)floorf(jx), c0 = (int)floorf(jy);
    int a1 = min(a0 + 1, DHH - 1), c1 = min(c0 + 1, DHH - 1);
    float ux = jx - (float)a0, uy = jy - (float)c0;
    const float* dp = depth + (size_t)b * DHH * DHH;
    float v = dp[c0 * DHH + a0] * (1.0f - ux) * (1.0f - uy) +
              dp[c0 * DHH + a1] * ux * (1.0f - uy) +
              dp[c1 * DHH + a0] * (1.0f - ux) * uy +
              dp[c1 * DHH + a1] * ux * uy;
    g_dep[row] = v;
}

// ---- 8-deep k micro-kernel, 8x8 tile, packed --------------------------------
__device__ __forceinline__ void mma_tile8(
    u64 acc64[8][4], const float (*As8)[68], const float (*Ws8)[128],
    int r8, int c16) {
#pragma unroll
    for (int kk = 0; kk < 8; kk++) {
        float4 a0 = *reinterpret_cast<const float4*>(&As8[kk][r8 * 4]);
        float4 a1 = *reinterpret_cast<const float4*>(&As8[kk][32 + r8 * 4]);
        ulonglong2 wva = *reinterpret_cast<const ulonglong2*>(&Ws8[kk][c16 * 8]);
        ulonglong2 wvb = *reinterpret_cast<const ulonglong2*>(&Ws8[kk][c16 * 8 + 4]);
        u64 wpk[4] = {wva.x, wva.y, wvb.x, wvb.y};
        u64 ab[8] = {bcast2(a0.x), bcast2(a0.y), bcast2(a0.z), bcast2(a0.w),
                     bcast2(a1.x), bcast2(a1.y), bcast2(a1.z), bcast2(a1.w)};
#pragma unroll
        for (int i = 0; i < 8; i++)
#pragma unroll
            for (int j = 0; j < 4; j++) fma2(acc64[i][j], ab[i], wpk[j]);
    }
}

// ---- group-1 -> group-0 reduction of acc rows [r*4, r*4+4) via red buffer ---
__device__ __forceinline__ void red_store(float* red, u64 acc64[8][4], int r, int wt) {
#pragma unroll
    for (int i = 0; i < 4; i++)
#pragma unroll
        for (int j = 0; j < 4; j++) {
            float lo, hi;
            unpack2(acc64[r * 4 + i][j], lo, hi);
            red[(i * 8 + 2 * j) * 128 + wt] = lo;
            red[(i * 8 + 2 * j + 1) * 128 + wt] = hi;
        }
}
__device__ __forceinline__ void red_add(const float* red, float accf[8][8], int r, int wt) {
#pragma unroll
    for (int i = 0; i < 4; i++)
#pragma unroll
        for (int j2 = 0; j2 < 8; j2++)
            accf[r * 4 + i][j2] += red[(i * 8 + j2) * 128 + wt];
}

// ---------------- 64x128 GEMM, 256 thr, K-split groups, cp.async W staging ---
template <int EPI>
__global__ void __launch_bounds__(256, 2)
gemm64x128(const float* __restrict__ A, const float* __restrict__ W,
           const float* __restrict__ bias, float* __restrict__ C,
           int K, int N) {
    __shared__ __align__(16) float As[2][16][68];
    __shared__ __align__(16) float Ws[2][16][128];

    int m0 = blockIdx.x * 64;
    int n0 = blockIdx.y * 128;
    int tid = threadIdx.x;
    int g   = tid >> 7;
    int wt  = tid & 127;
    int r8 = wt & 7, c16 = wt >> 3;

    int am = tid >> 2;
    int aq = (tid & 3) * 4;
    int wk = tid >> 5;             // 0..7
    int wn = (tid & 31) * 4;

    u64 acc64[8][4];
#pragma unroll
    for (int i = 0; i < 8; i++)
#pragma unroll
        for (int j = 0; j < 4; j++) acc64[i][j] = 0ull;

    // preload tile 0: A via regs, W via cp.async
    {
        float4 v = *reinterpret_cast<const float4*>(&A[(size_t)(m0 + am) * K + aq]);
        As[0][aq + 0][am] = v.x;
        As[0][aq + 1][am] = v.y;
        As[0][aq + 2][am] = v.z;
        As[0][aq + 3][am] = v.w;
#pragma unroll
        for (int i = 0; i < 2; i++) {
            int k = wk + i * 8;
            cp16(&Ws[0][k][wn], &W[(size_t)k * N + n0 + wn]);
        }
        cp_commit();
    }
    cp_wait0();
    __syncthreads();

    int KT = K >> 4;
    int p = 0;
    for (int t = 0; t < KT; t++) {
        float4 pa;
        bool has = (t + 1 < KT);
        int q = p ^ 1;
        if (has) {
            int k0 = (t + 1) << 4;
            // W for next tile: async into buffer q (safe: q drained at last sync)
#pragma unroll
            for (int i = 0; i < 2; i++) {
                int k = wk + i * 8;
                cp16(&Ws[q][k][wn], &W[(size_t)(k0 + k) * N + n0 + wn]);
            }
            cp_commit();
            pa = *reinterpret_cast<const float4*>(&A[(size_t)(m0 + am) * K + k0 + aq]);
        }

        mma_tile8(acc64,
                  reinterpret_cast<const float (*)[68]>(&As[p][g * 8][0]),
                  reinterpret_cast<const float (*)[128]>(&Ws[p][g * 8][0]),
                  r8, c16);

        if (has) {
            As[q][aq + 0][am] = pa.x;
            As[q][aq + 1][am] = pa.y;
            As[q][aq + 2][am] = pa.z;
            As[q][aq + 3][am] = pa.w;
            cp_wait0();
        }
        __syncthreads();
        p ^= 1;
    }

    // ---- cross-group reduction (red buffer aliases Ws: 4096 floats) ----
    float* red = &Ws[0][0][0];
    float accf[8][8];
    if (g == 0) {
#pragma unroll
        for (int i = 0; i < 8; i++)
#pragma unroll
            for (int j = 0; j < 4; j++) unpack2(acc64[i][j], accf[i][2 * j], accf[i][2 * j + 1]);
    }
#pragma unroll
    for (int r = 0; r < 2; r++) {
        if (g == 1) red_store(red, acc64, r, wt);
        __syncthreads();
        if (g == 0) red_add(red, accf, r, wt);
        __syncthreads();
    }

    if (g == 0) {
        float bb[8];
#pragma unroll
        for (int j = 0; j < 8; j++) bb[j] = bias[n0 + c16 * 8 + j];
#pragma unroll
        for (int h = 0; h < 2; h++) {
#pragma unroll
            for (int i = 0; i < 4; i++) {
                int m = m0 + h * 32 + r8 * 4 + i;
                int ai = h * 4 + i;
                float v[8];
#pragma unroll
                for (int j = 0; j < 8; j++) {
                    v[j] = accf[ai][j] + bb[j];
                    if (EPI == 0) v[j] = fmaxf(v[j], 0.0f);
                }
                float4* cp = reinterpret_cast<float4*>(&C[(size_t)m * N + n0 + c16 * 8]);
                cp[0] = make_float4(v[0], v[1], v[2], v[3]);
                cp[1] = make_float4(v[4], v[5], v[6], v[7]);
            }
        }
    }
}

// ---------------- small GEMM (N=16), used once for wi3 -----------------------
template <int BM, int BN, int BK, int TM, int TN, int EPI>
__global__ void gemm_kernel(const float* __restrict__ A,
                            const float* __restrict__ W,
                            const float* __restrict__ bias,
                            float* __restrict__ C,
                            int K, int N) {
    constexpr int TX = BN / TN;
    constexpr int TY = BM / TM;
    static_assert(TX * TY == 256, "256 threads");
    constexpr int AS = BM + 4;
    __shared__ float As[BK][AS];
    __shared__ float Ws[BK][BN];

    int m0 = blockIdx.x * BM;
    int n0 = blockIdx.y * BN;
    int tid = threadIdx.x;
    int tx = tid % TX, ty = tid / TX;

    float acc[TM][TN];
#pragma unroll
    for (int i = 0; i < TM; i++)
#pragma unroll
        for (int j = 0; j < TN; j++) acc[i][j] = 0.0f;

    int am = tid >> 2;
    int aq = (tid & 3) * 4;

    for (int k0 = 0; k0 < K; k0 += BK) {
        {
            const float4 v = *reinterpret_cast<const float4*>(
                &A[(size_t)(m0 + am) * K + k0 + aq]);
            As[aq + 0][am] = v.x;
            As[aq + 1][am] = v.y;
            As[aq + 2][am] = v.z;
            As[aq + 3][am] = v.w;
        }
        for (int i = tid; i < BK * BN; i += 256) {
            int k = i / BN, n = i % BN;
            Ws[k][n] = W[(size_t)(k0 + k) * N + n0 + n];
        }
        __syncthreads();
#pragma unroll
        for (int kk = 0; kk < BK; kk++) {
            float a[TM], w[TN];
#pragma unroll
            for (int i = 0; i < TM; i++) a[i] = As[kk][ty * TM + i];
#pragma unroll
            for (int j = 0; j < TN; j++) w[j] = Ws[kk][tx * TN + j];
#pragma unroll
            for (int i = 0; i < TM; i++)
#pragma unroll
                for (int j = 0; j < TN; j++) acc[i][j] += a[i] * w[j];
        }
        __syncthreads();
    }
#pragma unroll
    for (int i = 0; i < TM; i++) {
        int m = m0 + ty * TM + i;
#pragma unroll
        for (int j = 0; j < TN; j++) {
            int n = n0 + tx * TN + j;
            float v = acc[i][j] + bias[n];
            if (EPI == 0) v = fmaxf(v, 0.0f);
            C[(size_t)m * N + n] = v;
        }
    }
}

// ---------------- fused wp2 -> wu1 -> wu2 -> state update --------------------
__global__ void __launch_bounds__(256, 2)
fused_step(const float* __restrict__ A,           // g_bufA (h1), row len 256
           const float* __restrict__ wp2, const float* __restrict__ bp2,
           const float* __restrict__ wu1, const float* __restrict__ bu1,
           const float* __restrict__ wu2, const float* __restrict__ bu2,
           const float* __restrict__ sstep,
           float* __restrict__ state) {
    extern __shared__ __align__(16) float dyn[];
    float (*As)[16][68]  = reinterpret_cast<float (*)[16][68]>(dyn + FS_AS_OFF);
    float (*Ws)[16][128] = reinterpret_cast<float (*)[16][128]>(dyn + FS_WS_OFF);
    float (*Hs)[68]      = reinterpret_cast<float (*)[68]>(dyn + FS_HS_OFF);
    float* redH = dyn + FS_HS_OFF;
    float* bp2s = dyn + FS_B1_OFF;
    float* bu1s = dyn + FS_B2_OFF;
    float* bu2s = dyn + FS_B3_OFF;

    int m0 = blockIdx.x * 64;
    int tid = threadIdx.x;
    int g   = tid >> 7;
    int wt  = tid & 127;
    int r8 = wt & 7, c16 = wt >> 3;
    int am = tid >> 2;
    int aq = (tid & 3) * 4;
    int wk = tid >> 5;
    int wn = (tid & 31) * 4;

    if (tid < 128) { bp2s[tid] = bp2[tid]; bu1s[tid] = bu1[tid]; }
    if (tid < 16)  { bu2s[tid] = bu2[tid]; }

    u64 acc64[8][4];
#pragma unroll
    for (int i = 0; i < 8; i++)
#pragma unroll
        for (int j = 0; j < 4; j++) acc64[i][j] = 0ull;

    // ---- phase 1: h2 = relu(h1 @ wp2 + bp2), K=256 ----
    {
        float4 v = *reinterpret_cast<const float4*>(&A[(size_t)(m0 + am) * 256 + aq]);
        As[0][aq + 0][am] = v.x;
        As[0][aq + 1][am] = v.y;
        As[0][aq + 2][am] = v.z;
        As[0][aq + 3][am] = v.w;
#pragma unroll
        for (int i = 0; i < 2; i++) {
            int k = wk + i * 8;
            cp16(&Ws[0][k][wn], &wp2[(size_t)k * 128 + wn]);
        }
        cp_commit();
    }
    cp_wait0();
    __syncthreads();

    int p = 0;
    for (int t = 0; t < 16; t++) {
        float4 pa;
        bool has = (t + 1 < 16);
        int q = p ^ 1;
        if (has) {
            int k0 = (t + 1) << 4;
#pragma unroll
            for (int i = 0; i < 2; i++) {
                int k = wk + i * 8;
                cp16(&Ws[q][k][wn], &wp2[(size_t)(k0 + k) * 128 + wn]);
            }
            cp_commit();
            pa = *reinterpret_cast<const float4*>(&A[(size_t)(m0 + am) * 256 + k0 + aq]);
        }
        mma_tile8(acc64,
                  reinterpret_cast<const float (*)[68]>(&As[p][g * 8][0]),
                  reinterpret_cast<const float (*)[128]>(&Ws[p][g * 8][0]),
                  r8, c16);
        if (has) {
            As[q][aq + 0][am] = pa.x;
            As[q][aq + 1][am] = pa.y;
            As[q][aq + 2][am] = pa.z;
            As[q][aq + 3][am] = pa.w;
            cp_wait0();
        }
        __syncthreads();
        p ^= 1;
    }

    // reduction (redH = Hs area) + h2 store + wu1 tile-0 async stage
    {
        float accf[8][8];
        if (g == 0) {
#pragma unroll
            for (int i = 0; i < 8; i++)
#pragma unroll
                for (int j = 0; j < 4; j++) unpack2(acc64[i][j], accf[i][2 * j], accf[i][2 * j + 1]);
        }
#pragma unroll
        for (int r = 0; r < 2; r++) {
            if (g == 1) red_store(redH, acc64, r, wt);
            __syncthreads();
            if (g == 0) red_add(redH, accf, r, wt);
            __syncthreads();
        }
        if (g == 0) {
#pragma unroll
            for (int j = 0; j < 8; j++) {
                int n = c16 * 8 + j;
                float v0[4], v1[4];
#pragma unroll
                for (int i = 0; i < 4; i++) v0[i] = fmaxf(accf[i][j] + bp2s[n], 0.0f);
#pragma unroll
                for (int i = 0; i < 4; i++) v1[i] = fmaxf(accf[4 + i][j] + bp2s[n], 0.0f);
                *reinterpret_cast<float4*>(&Hs[n][r8 * 4])      = make_float4(v0[0], v0[1], v0[2], v0[3]);
                *reinterpret_cast<float4*>(&Hs[n][32 + r8 * 4]) = make_float4(v1[0], v1[1], v1[2], v1[3]);
            }
        }
#pragma unroll
        for (int i = 0; i < 2; i++) {
            int k = wk + i * 8;
            cp16(&Ws[0][k][wn], &wu1[(size_t)k * 128 + wn]);
        }
        cp_commit();
        cp_wait0();
        __syncthreads();
    }

    // ---- phase 2: dh = relu(h2 @ wu1 + bu1), K=128, A in Hs ----
#pragma unroll
    for (int i = 0; i < 8; i++)
#pragma unroll
        for (int j = 0; j < 4; j++) acc64[i][j] = 0ull;

    p = 0;
    for (int c = 0; c < 8; c++) {
        bool has = (c + 1 < 8);
        int q = p ^ 1;
        if (has) {
            int k0 = (c + 1) << 4;
#pragma unroll
            for (int i = 0; i < 2; i++) {
                int k = wk + i * 8;
                cp16(&Ws[q][k][wn], &wu1[(size_t)(k0 + k) * 128 + wn]);
            }
            cp_commit();
        }
        mma_tile8(acc64,
                  reinterpret_cast<const float (*)[68]>(&Hs[c * 16 + g * 8][0]),
                  reinterpret_cast<const float (*)[128]>(&Ws[p][g * 8][0]),
                  r8, c16);
        if (has) cp_wait0();
        __syncthreads();
        p ^= 1;
    }

    // reduction (redH) + dh store + wu2 staging
    {
        float accf[8][8];
        if (g == 0) {
#pragma unroll
            for (int i = 0; i < 8; i++)
#pragma unroll
                for (int j = 0; j < 4; j++) unpack2(acc64[i][j], accf[i][2 * j], accf[i][2 * j + 1]);
        }
#pragma unroll
        for (int r = 0; r < 2; r++) {
            if (g == 1) red_store(redH, acc64, r, wt);
            __syncthreads();
            if (g == 0) red_add(redH, accf, r, wt);
            __syncthreads();
        }
        if (g == 0) {
#pragma unroll
            for (int j = 0; j < 8; j++) {
                int n = c16 * 8 + j;
                float v0[4], v1[4];
#pragma unroll
                for (int i = 0; i < 4; i++) v0[i] = fmaxf(accf[i][j] + bu1s[n], 0.0f);
#pragma unroll
                for (int i = 0; i < 4; i++) v1[i] = fmaxf(accf[4 + i][j] + bu1s[n], 0.0f);
                *reinterpret_cast<float4*>(&Hs[n][r8 * 4])      = make_float4(v0[0], v0[1], v0[2], v0[3]);
                *reinterpret_cast<float4*>(&Hs[n][32 + r8 * 4]) = make_float4(v1[0], v1[1], v1[2], v1[3]);
            }
        }
        {
            float* wflat = &Ws[0][0][0];
#pragma unroll
            for (int i = 0; i < 2; i++) {
                int f = (tid + i * 256) * 4;   // 2048 floats
                cp16(&wflat[f], &wu2[f]);
            }
            cp_commit();
            cp_wait0();
        }
        __syncthreads();
    }

    // ---- phase 3: delta = dh @ wu2 + bu2; state += step*delta ----
    {
        const float* wflat = &Ws[0][0][0];
        int col = tid & 15;
        int rg  = tid >> 4;   // 0..15 -> rows rg*4..+3
        float acc3[4];
#pragma unroll
        for (int i = 0; i < 4; i++) acc3[i] = 0.0f;
#pragma unroll 8
        for (int kk = 0; kk < 128; kk++) {
            float w = wflat[kk * 16 + col];
            float4 a4 = *reinterpret_cast<const float4*>(&Hs[kk][rg * 4]);
            acc3[0] += a4.x * w; acc3[1] += a4.y * w;
            acc3[2] += a4.z * w; acc3[3] += a4.w * w;
        }
        float stp = sstep[0];
        float bv = bu2s[col];
#pragma unroll
        for (int i = 0; i < 4; i++) {
            int m = m0 + rg * 4 + i;
            state[(size_t)m * SD + col] += stp * (acc3[i] + bv);
        }
    }
}

// ---------------- initial state build ----------------------------------------
__global__ void init_state_kernel(const float* __restrict__ sx,
                                  const float* __restrict__ sy,
                                  const float* __restrict__ doff) {
    int row = blockIdx.x * blockDim.x + threadIdx.x;
    if (row >= NROWS) return;
    int n = row % NP;
    const float* ini = g_init + (size_t)row * SD;
    float* st = g_state + (size_t)row * SD;
    st[0] = sx[n] + ini[0] * 0.15f;
    st[1] = sy[n] + ini[1] * 0.15f;
    st[2] = doff[0] + g_dep[row] * -2.0f;
#pragma unroll
    for (int i = 3; i < SD; i++) st[i] = ini[i];
}

// ---------------- fused kNN + pin gather (2 blocks per batch) ----------------
__global__ void __launch_bounds__(384) neighpin_kernel() {
    __shared__ float st[NP * SD];   // 24128 B
    int b = blockIdx.x >> 1;
    int half = blockIdx.x & 1;
    int t = threadIdx.x;

    const float4* gs = reinterpret_cast<const float4*>(g_state + (size_t)b * NP * SD);
    float4* s4 = reinterpret_cast<float4*>(st);
    for (int i = t; i < NP * SD / 4; i += 384) s4[i] = gs[i];
    __syncthreads();

    int pt = half * 189 + t;
    if (t >= 189 || pt >= NP) return;

    float bd[KNEI + 1];
    int bi[KNEI + 1];
#pragma unroll
    for (int i = 0; i <= KNEI; i++) { bd[i] = 3.4e38f; bi[i] = -1; }

    float x = st[pt * SD + 0], y = st[pt * SD + 1], z = st[pt * SD + 2];
    for (int j = 0; j < NP; j++) {
        float dx = x - st[j * SD + 0];
        float dy = y - st[j * SD + 1];
        float dz = z - st[j * SD + 2];
        float d2 = dx * dx + dy * dy + dz * dz;
        if (d2 < bd[KNEI]) {
            int p = KNEI;
            while (p > 0 && bd[p - 1] > d2) {
                bd[p] = bd[p - 1];
                bi[p] = bi[p - 1];
                p--;
            }
            bd[p] = d2;
            bi[p] = j;
        }
    }

    float4* p4 = reinterpret_cast<float4*>(g_pin + (size_t)(b * NP + pt) * PIN_DIM);
    const float4* self = reinterpret_cast<const float4*>(&st[pt * SD]);
#pragma unroll
    for (int q = 0; q < 4; q++) p4[q] = self[q];
#pragma unroll
    for (int k = 0; k < KNEI; k++) {
        const float4* nb = reinterpret_cast<const float4*>(&st[bi[k + 1] * SD]);
#pragma unroll
        for (int q = 0; q < 4; q++) p4[4 + k * 4 + q] = nb[q];
    }
}

// ---------------- postprocess ------------------------------------------------
__device__ __forceinline__ float sgnf(float x) {
    return (x > 0.0f) ? 1.0f : ((x < 0.0f) ? -1.0f : 0.0f);
}

__global__ void final_kernel(float* __restrict__ out) {
    int row = blockIdx.x * blockDim.x + threadIdx.x;
    if (row >= NROWS) return;
    const float* s = g_state + (size_t)row * SD;
    float o[14];
    o[0] = s[0]; o[1] = s[1]; o[2] = s[2];

#pragma unroll
    for (int i = 0; i < 3; i++) {
        float tv = fminf(fmaxf(s[3 + i], -10.0f), 20.0f) + 1.0f;
        float sp = log1pf(expf(tv));
        o[3 + i] = fminf(fmaxf(sp * 0.15f, 1e-6f), 2.0f);
    }

    const float eps = 1e-8f;
    float a1x = s[6], a1y = s[7], a1z = s[8];
    float a2x = s[9], a2y = s[10], a2z = s[11];
    float n1 = sqrtf(a1x * a1x + a1y * a1y + a1z * a1z) + eps;
    float b1x = a1x / n1, b1y = a1y / n1, b1z = a1z / n1;
    float dd = b1x * a2x + b1y * a2y + b1z * a2z;
    float pxv = a2x - dd * b1x, pyv = a2y - dd * b1y, pzv = a2z - dd * b1z;
    float n2 = sqrtf(pxv * pxv + pyv * pyv + pzv * pzv) + eps;
    float b2x = pxv / n2, b2y = pyv / n2, b2z = pzv / n2;
    float b3x = b1y * b2z - b1z * b2y;
    float b3y = b1z * b2x - b1x * b2z;
    float b3z = b1x * b2y - b1y * b2x;
    float m00 = b1x, m11 = b2y, m22 = b3z;
    float qw = 0.5f * sqrtf(fmaxf(1.0f + m00 + m11 + m22, 0.0f) + eps);
    float qx = 0.5f * sqrtf(fmaxf(1.0f + m00 - m11 - m22, 0.0f) + eps) * sgnf(b2z - b3y);
    float qy = 0.5f * sqrtf(fmaxf(1.0f - m00 + m11 - m22, 0.0f) + eps) * sgnf(b3x - b1z);
    float qz = 0.5f * sqrtf(fmaxf(1.0f - m00 - m11 + m22, 0.0f) + eps) * sgnf(b1y - b2x);
    float qn = sqrtf(qw * qw + qx * qx + qy * qy + qz * qz) + eps;
    o[6] = qw / qn; o[7] = qx / qn; o[8] = qy / qn; o[9] = qz / qn;

    o[10] = 1.0f / (1.0f + expf(-s[12]));
    o[11] = 1.0f / (1.0f + expf(-s[13]));
    o[12] = 1.0f / (1.0f + expf(-s[14]));
    o[13] = 1.0f / (1.0f + expf(-s[15]));

    float* op = out + (size_t)row * 14;
#pragma unroll
    for (int i = 0; i < 14; i++) op[i] = o[i];
}

// ---------------- launch ------------------------------------------------------
extern "C" void kernel_launch(void* const* d_in, const int* in_sizes, int n_in,
                              void* d_out, int out_size) {
    const float* feat  = (const float*)d_in[0];
    const float* depth = (const float*)d_in[1];
    const float* sx    = (const float*)d_in[2];
    const float* sy    = (const float*)d_in[3];
    const float* doff  = (const float*)d_in[4];
    const float* sstep = (const float*)d_in[5];
    const float* wi1 = (const float*)d_in[6];
    const float* bi1 = (const float*)d_in[7];
    const float* wi2 = (const float*)d_in[8];
    const float* bi2 = (const float*)d_in[9];
    const float* wi3 = (const float*)d_in[10];
    const float* bi3 = (const float*)d_in[11];
    const float* wp1 = (const float*)d_in[12];
    const float* bp1 = (const float*)d_in[13];
    const float* wp2 = (const float*)d_in[14];
    const float* bp2 = (const float*)d_in[15];
    const float* wu1 = (const float*)d_in[16];
    const float* bu1 = (const float*)d_in[17];
    const float* wu2 = (const float*)d_in[18];
    const float* bu2 = (const float*)d_in[19];

    cudaFuncSetAttribute(fused_step, cudaFuncAttributeMaxDynamicSharedMemorySize,
                         FS_TOTAL_B);

    void *pFs, *pA, *pB, *pInit, *pState, *pPin;
    cudaGetSymbolAddress(&pFs, g_Fs);
    cudaGetSymbolAddress(&pA, g_bufA);
    cudaGetSymbolAddress(&pB, g_bufB);
    cudaGetSymbolAddress(&pInit, g_init);
    cudaGetSymbolAddress(&pState, g_state);
    cudaGetSymbolAddress(&pPin, g_pin);
    float* Fs = (float*)pFs;
    float* bufA = (float*)pA;
    float* bufB = (float*)pB;
    float* initb = (float*)pInit;
    float* state = (float*)pState;
    float* pin = (float*)pPin;

    const int MB = NROWS / 64;  // 377

    // launches 0,1: sampling (launch #3 = gemm64x128 wi2 for ncu)
    sample_feat_kernel<<<dim3(BB, CIN / CCHUNK), 256>>>(feat, sx, sy);
    sample_depth_kernel<<<(NROWS + 127) / 128, 128>>>(depth, sx, sy);

    // launch 2: wi1 (K=384, N=256); launch 3: wi2 (K=256, N=128) <- profiled
    gemm64x128<0><<<dim3(MB, 2), 256>>>(Fs, wi1, bi1, bufA, CIN, H2X);
    gemm64x128<0><<<dim3(MB, 1), 256>>>(bufA, wi2, bi2, bufB, H2X, HID);
    gemm_kernel<64, 16, 16, 4, 1, 1><<<dim3(MB, 1), 256>>>(bufB, wi3, bi3, initb, HID, SD);

    init_state_kernel<<<(NROWS + 255) / 256, 256>>>(sx, sy, doff);

    for (int s = 0; s < NSTEPS; s++) {
        neighpin_kernel<<<BB * 2, 384>>>();
        gemm64x128<0><<<dim3(MB, 2), 256>>>(pin, wp1, bp1, bufA, PIN_DIM, H2X);
        fused_step<<<MB, 256, FS_TOTAL_B>>>(bufA, wp2, bp2, wu1, bu1, wu2, bu2, sstep, state);
    }

    final_kernel<<<(NROWS + 255) / 256, 256>>>((float*)d_out);
}